// round 1
// baseline (speedup 1.0000x reference)
#include <cuda_runtime.h>

// Pink noise: 6-pole diagonal IIR + 1-sample delay, exact chunked scan.
// white[B, L] -> pink[B, L], B=out_size/L, L=65536.
//
// Per channel: 512 threads, each owns a contiguous 128-sample chunk.
//   Pass A: run recurrence from zero state per chunk (u-space), get particular state P_j.
//   Scan:   block-wide shuffle scan over chunk states with diagonal multipliers a_i^128.
//   Pass B: re-run each chunk from its exact entry state, emit output.
// All global traffic staged through padded smem for full coalescing.

#define NT      512
#define CHUNK   128
#define TILE_I  32
#define NTILES  (CHUNK / TILE_I)      // 4
#define LROW    65536
#define SSTRIDE (TILE_I + 1)          // 33 floats, conflict-free
#define NW      (NT / 32)             // 16 warps

__device__ __forceinline__ void stage_load(float* tile, const float* __restrict__ grow,
                                           int k, int tid) {
#pragma unroll
    for (int r = 0; r < 8; r++) {
        int j  = r * 64 + (tid >> 3);
        int i4 = (tid & 7) * 4;
        float4 v = *reinterpret_cast<const float4*>(grow + j * CHUNK + k * TILE_I + i4);
        float* dst = &tile[j * SSTRIDE + i4];
        dst[0] = v.x; dst[1] = v.y; dst[2] = v.z; dst[3] = v.w;
    }
}

__global__ void __launch_bounds__(NT, 2)
pink_kernel(const float* __restrict__ white, float* __restrict__ out) {
    extern __shared__ float tile[];          // NT * SSTRIDE floats
    __shared__ float warpT[NW][6];
    __shared__ float warpW[NW][6];

    const float A0 = 0.99886f, A1 = 0.99332f, A2 = 0.969f,
                A3 = 0.8665f,  A4 = 0.55f,    A5 = -0.7616f;
    const float C0 = 0.0555179f, C1 = 0.0750759f, C2 = 0.153852f,
                C3 = 0.3104856f, C4 = 0.5329522f, C5 = -0.016898f;
    const float B6G = 0.115926f, DIRECT = 0.5362f, OUTG = 0.11f;

    const int tid  = threadIdx.x;
    const int lane = tid & 31;
    const int wid  = tid >> 5;
    const float* wrow = white + (size_t)blockIdx.x * LROW;
    float*       orow = out   + (size_t)blockIdx.x * LROW;

    // ---------------- Pass A: particular state from zero init ----------------
    float u0 = 0.f, u1 = 0.f, u2 = 0.f, u3 = 0.f, u4 = 0.f, u5 = 0.f;
    for (int k = 0; k < NTILES; k++) {
        __syncthreads();
        stage_load(tile, wrow, k, tid);
        __syncthreads();
        const float* src = &tile[tid * SSTRIDE];
#pragma unroll
        for (int i = 0; i < TILE_I; i++) {
            float w = src[i];
            u0 = fmaf(A0, u0, w); u1 = fmaf(A1, u1, w); u2 = fmaf(A2, u2, w);
            u3 = fmaf(A3, u3, w); u4 = fmaf(A4, u4, w); u5 = fmaf(A5, u5, w);
        }
    }

    // ---------------- Block scan over chunk states (u-space) ----------------
    float p[6] = {u0, u1, u2, u3, u4, u5};
    float m[6];                         // a_i^128 via 7 squarings (positive, even power)
    {
        const float a[6] = {A0, A1, A2, A3, A4, A5};
#pragma unroll
        for (int i = 0; i < 6; i++) {
            float t = a[i];
#pragma unroll
            for (int s = 0; s < 7; s++) t *= t;
            m[i] = t;
        }
    }
    float mult[6];
#pragma unroll
    for (int i = 0; i < 6; i++) mult[i] = m[i];

    // warp-level inclusive scan: S_l = m*S_{l-1} + P_l
#pragma unroll
    for (int o = 1; o < 32; o <<= 1) {
#pragma unroll
        for (int i = 0; i < 6; i++) {
            float up = __shfl_up_sync(0xffffffffu, p[i], o);
            if (lane >= o) p[i] = fmaf(mult[i], up, p[i]);
            mult[i] *= mult[i];
        }
    }
    // now mult[i] == m[i]^32
    float excl[6];
#pragma unroll
    for (int i = 0; i < 6; i++) {
        float e = __shfl_up_sync(0xffffffffu, p[i], 1);
        excl[i] = (lane == 0) ? 0.f : e;
    }
    if (lane == 31) {
#pragma unroll
        for (int i = 0; i < 6; i++) warpT[wid][i] = p[i];
    }
    __syncthreads();

    if (wid == 0) {
        float t[6], cm[6];
#pragma unroll
        for (int i = 0; i < 6; i++) {
            t[i]  = (lane < NW) ? warpT[lane][i] : 0.f;
            cm[i] = mult[i];            // m^32
        }
#pragma unroll
        for (int o = 1; o < NW; o <<= 1) {
#pragma unroll
            for (int i = 0; i < 6; i++) {
                float up = __shfl_up_sync(0xffffffffu, t[i], o);
                if (lane >= o) t[i] = fmaf(cm[i], up, t[i]);
                cm[i] *= cm[i];
            }
        }
        if (lane < NW) {
#pragma unroll
            for (int i = 0; i < 6; i++) warpW[lane][i] = t[i];
        }
    }
    __syncthreads();

    // entry state for this chunk: excl + m^lane * (state after previous warps)
    float E[6];
    {
        float f[6];
#pragma unroll
        for (int i = 0; i < 6; i++) {
            float b = m[i], r = 1.f;
            int e = lane;
#pragma unroll
            for (int s = 0; s < 5; s++) { if (e & 1) r *= b; b *= b; e >>= 1; }
            f[i] = r;
        }
#pragma unroll
        for (int i = 0; i < 6; i++)
            E[i] = excl[i] + ((wid == 0) ? 0.f : f[i] * warpW[wid - 1][i]);
    }

    // ---------------- Pass B: exact recompute + output ----------------
    u0 = E[0]; u1 = E[1]; u2 = E[2]; u3 = E[3]; u4 = E[4]; u5 = E[5];
    float prev_w = (tid == 0) ? 0.f : wrow[tid * CHUNK - 1];

    for (int k = 0; k < NTILES; k++) {
        __syncthreads();
        stage_load(tile, wrow, k, tid);
        __syncthreads();
        float* src = &tile[tid * SSTRIDE];
#pragma unroll
        for (int i = 0; i < TILE_I; i++) {
            float w = src[i];
            u0 = fmaf(A0, u0, w); u1 = fmaf(A1, u1, w); u2 = fmaf(A2, u2, w);
            u3 = fmaf(A3, u3, w); u4 = fmaf(A4, u4, w); u5 = fmaf(A5, u5, w);
            float s = fmaf(C0, u0,
                      fmaf(C1, u1,
                      fmaf(C2, u2,
                      fmaf(C3, u3,
                      fmaf(C4, u4, C5 * u5)))));
            s = fmaf(B6G, prev_w, s);
            s = fmaf(DIRECT, w, s);
            src[i] = OUTG * s;
            prev_w = w;
        }
        __syncthreads();
#pragma unroll
        for (int r = 0; r < 8; r++) {
            int j  = r * 64 + (tid >> 3);
            int i4 = (tid & 7) * 4;
            const float* sp = &tile[j * SSTRIDE + i4];
            float4 v = make_float4(sp[0], sp[1], sp[2], sp[3]);
            *reinterpret_cast<float4*>(orow + j * CHUNK + k * TILE_I + i4) = v;
        }
    }
}

extern "C" void kernel_launch(void* const* d_in, const int* in_sizes, int n_in,
                              void* d_out, int out_size) {
    const float* white = (const float*)d_in[0];
    float* out = (float*)d_out;
    int B = out_size / LROW;

    size_t smem = (size_t)NT * SSTRIDE * sizeof(float);   // 67584 bytes
    cudaFuncSetAttribute(pink_kernel, cudaFuncAttributeMaxDynamicSharedMemorySize,
                         (int)smem);
    pink_kernel<<<B, NT, smem>>>(white, out);
}

// round 2
// speedup vs baseline: 1.0741x; 1.0741x over previous
#include <cuda_runtime.h>

// Pink noise: 6-pole diagonal IIR + 1-sample delay, exact chunked scan.
// white[B, L] -> pink[B, L], B=out_size/L, L=65536.
//
// Per channel: 512 threads, each owns a contiguous 128-sample chunk.
//   Pass A: run recurrence from zero state per chunk (u-space, f32x2-packed poles).
//   Scan:   block-wide shuffle scan over chunk states with diagonal multipliers a_i^128.
//   Pass B: re-run each chunk from its exact entry state, emit output.
// All global traffic staged through padded smem (float4 both directions, SSTRIDE=36
// => conflict-free for both coalesced-stage and thread-sequential-consume patterns).

#define NT      512
#define CHUNK   128
#define TILE_I  32
#define NTILES  (CHUNK / TILE_I)      // 4
#define LROW    65536
#define SSTRIDE 36                    // mult of 4 (float4-aligned), 36 mod 32 = 4 -> conflict-free
#define NW      (NT / 32)             // 16 warps

typedef unsigned long long ull;

__device__ __forceinline__ ull pk2(float lo, float hi) {
    ull r; asm("mov.b64 %0, {%1, %2};" : "=l"(r) : "f"(lo), "f"(hi)); return r;
}
__device__ __forceinline__ void upk2(ull v, float& lo, float& hi) {
    asm("mov.b64 {%0, %1}, %2;" : "=f"(lo), "=f"(hi) : "l"(v));
}
__device__ __forceinline__ ull ffma2(ull a, ull b, ull c) {
    ull d; asm("fma.rn.f32x2 %0, %1, %2, %3;" : "=l"(d) : "l"(a), "l"(b), "l"(c)); return d;
}
__device__ __forceinline__ ull fmul2(ull a, ull b) {
    ull d; asm("mul.rn.f32x2 %0, %1, %2;" : "=l"(d) : "l"(a), "l"(b)); return d;
}

__device__ __forceinline__ void stage_load(float* tile, const float* __restrict__ grow,
                                           int k, int tid) {
#pragma unroll
    for (int r = 0; r < 8; r++) {
        int j  = r * 64 + (tid >> 3);
        int i4 = (tid & 7) * 4;
        float4 v = *reinterpret_cast<const float4*>(grow + j * CHUNK + k * TILE_I + i4);
        *reinterpret_cast<float4*>(&tile[j * SSTRIDE + i4]) = v;
    }
}

__global__ void __launch_bounds__(NT, 2)
pink_kernel(const float* __restrict__ white, float* __restrict__ out) {
    extern __shared__ float tile[];          // NT * SSTRIDE floats
    __shared__ float warpT[NW][6];
    __shared__ float warpW[NW][6];

    const float A0 = 0.99886f, A1 = 0.99332f, A2 = 0.969f,
                A3 = 0.8665f,  A4 = 0.55f,    A5 = -0.7616f;
    const float C0 = 0.0555179f, C1 = 0.0750759f, C2 = 0.153852f,
                C3 = 0.3104856f, C4 = 0.5329522f, C5 = -0.016898f;
    const float B6G = 0.115926f, DIRECT = 0.5362f, OUTG = 0.11f;

    const int tid  = threadIdx.x;
    const int lane = tid & 31;
    const int wid  = tid >> 5;
    const float* wrow = white + (size_t)blockIdx.x * LROW;
    float*       orow = out   + (size_t)blockIdx.x * LROW;

    const ull A01 = pk2(A0, A1), A23 = pk2(A2, A3), A45 = pk2(A4, A5);

    // ---------------- Pass A: particular state from zero init ----------------
    ull U01 = 0ull, U23 = 0ull, U45 = 0ull;
    for (int k = 0; k < NTILES; k++) {
        __syncthreads();
        stage_load(tile, wrow, k, tid);
        __syncthreads();
        const float4* src = reinterpret_cast<const float4*>(&tile[tid * SSTRIDE]);
#pragma unroll
        for (int q = 0; q < 8; q++) {
            float4 wv = src[q];
            float ws[4] = {wv.x, wv.y, wv.z, wv.w};
#pragma unroll
            for (int c = 0; c < 4; c++) {
                ull W = pk2(ws[c], ws[c]);
                U01 = ffma2(A01, U01, W);
                U23 = ffma2(A23, U23, W);
                U45 = ffma2(A45, U45, W);
            }
        }
    }

    // ---------------- Block scan over chunk states (u-space) ----------------
    float p[6];
    upk2(U01, p[0], p[1]); upk2(U23, p[2], p[3]); upk2(U45, p[4], p[5]);
    float m[6];                         // a_i^128 via 7 squarings (positive, even power)
    {
        const float a[6] = {A0, A1, A2, A3, A4, A5};
#pragma unroll
        for (int i = 0; i < 6; i++) {
            float t = a[i];
#pragma unroll
            for (int s = 0; s < 7; s++) t *= t;
            m[i] = t;
        }
    }
    float mult[6];
#pragma unroll
    for (int i = 0; i < 6; i++) mult[i] = m[i];

    // warp-level inclusive scan: S_l = m*S_{l-1} + P_l
#pragma unroll
    for (int o = 1; o < 32; o <<= 1) {
#pragma unroll
        for (int i = 0; i < 6; i++) {
            float up = __shfl_up_sync(0xffffffffu, p[i], o);
            if (lane >= o) p[i] = fmaf(mult[i], up, p[i]);
            mult[i] *= mult[i];
        }
    }
    // now mult[i] == m[i]^32
    float excl[6];
#pragma unroll
    for (int i = 0; i < 6; i++) {
        float e = __shfl_up_sync(0xffffffffu, p[i], 1);
        excl[i] = (lane == 0) ? 0.f : e;
    }
    if (lane == 31) {
#pragma unroll
        for (int i = 0; i < 6; i++) warpT[wid][i] = p[i];
    }
    __syncthreads();

    if (wid == 0) {
        float t[6], cm[6];
#pragma unroll
        for (int i = 0; i < 6; i++) {
            t[i]  = (lane < NW) ? warpT[lane][i] : 0.f;
            cm[i] = mult[i];            // m^32
        }
#pragma unroll
        for (int o = 1; o < NW; o <<= 1) {
#pragma unroll
            for (int i = 0; i < 6; i++) {
                float up = __shfl_up_sync(0xffffffffu, t[i], o);
                if (lane >= o) t[i] = fmaf(cm[i], up, t[i]);
                cm[i] *= cm[i];
            }
        }
        if (lane < NW) {
#pragma unroll
            for (int i = 0; i < 6; i++) warpW[lane][i] = t[i];
        }
    }
    __syncthreads();

    // entry state for this chunk: excl + m^lane * (state after previous warps)
    float E[6];
    {
#pragma unroll
        for (int i = 0; i < 6; i++) {
            float b = m[i], r = 1.f;
            int e = lane;
#pragma unroll
            for (int s = 0; s < 5; s++) { if (e & 1) r *= b; b *= b; e >>= 1; }
            E[i] = excl[i] + ((wid == 0) ? 0.f : r * warpW[wid - 1][i]);
        }
    }

    // ---------------- Pass B: exact recompute + output ----------------
    U01 = pk2(E[0], E[1]); U23 = pk2(E[2], E[3]); U45 = pk2(E[4], E[5]);
    const ull C01 = pk2(C0, C1), C23 = pk2(C2, C3), C45 = pk2(C4, C5);
    float prev_w = (tid == 0) ? 0.f : wrow[tid * CHUNK - 1];

    for (int k = 0; k < NTILES; k++) {
        __syncthreads();
        stage_load(tile, wrow, k, tid);
        __syncthreads();
        float4* srcv = reinterpret_cast<float4*>(&tile[tid * SSTRIDE]);
#pragma unroll
        for (int q = 0; q < 8; q++) {
            float4 wv = srcv[q];
            float ws[4] = {wv.x, wv.y, wv.z, wv.w};
            float o4[4];
#pragma unroll
            for (int c = 0; c < 4; c++) {
                float w = ws[c];
                ull W = pk2(w, w);
                U01 = ffma2(A01, U01, W);
                U23 = ffma2(A23, U23, W);
                U45 = ffma2(A45, U45, W);
                ull P = ffma2(C01, U01, ffma2(C23, U23, fmul2(C45, U45)));
                float plo, phi;
                upk2(P, plo, phi);
                float s = plo + phi;
                s = fmaf(B6G, prev_w, s);
                s = fmaf(DIRECT, w, s);
                o4[c] = OUTG * s;
                prev_w = w;
            }
            srcv[q] = make_float4(o4[0], o4[1], o4[2], o4[3]);
        }
        __syncthreads();
#pragma unroll
        for (int r = 0; r < 8; r++) {
            int j  = r * 64 + (tid >> 3);
            int i4 = (tid & 7) * 4;
            float4 v = *reinterpret_cast<const float4*>(&tile[j * SSTRIDE + i4]);
            *reinterpret_cast<float4*>(orow + j * CHUNK + k * TILE_I + i4) = v;
        }
    }
}

extern "C" void kernel_launch(void* const* d_in, const int* in_sizes, int n_in,
                              void* d_out, int out_size) {
    const float* white = (const float*)d_in[0];
    float* out = (float*)d_out;
    int B = out_size / LROW;

    size_t smem = (size_t)NT * SSTRIDE * sizeof(float);   // 73728 bytes
    cudaFuncSetAttribute(pink_kernel, cudaFuncAttributeMaxDynamicSharedMemorySize,
                         (int)smem);
    pink_kernel<<<B, NT, smem>>>(white, out);
}

// round 4
// speedup vs baseline: 1.4476x; 1.3478x over previous
#include <cuda_runtime.h>
#include <cstdint>

// Pink noise: 6-pole diagonal IIR + 1-sample delay, exact chunked scan.
// white[B, L] -> pink[B, L], L=65536, one block per channel.
//
// v3 (resubmit — round 3 failed on container infra, not the kernel):
// cp.async staging + double-buffered tile pipeline (fetch k+1 overlaps
// compute k), f32x2-packed pole math, OUT_GAIN folded into output constants.

#define NT      512
#define CHUNK   128
#define TILE_I  16
#define NTILES  (CHUNK / TILE_I)      // 8
#define LROW    65536
#define SSTRIDE 20                    // conflict-free consume (20*l mod 32 distinct per phase)
#define NW      (NT / 32)             // 16 warps
#define BUF_FLOATS (NT * SSTRIDE)     // 10240 floats = 40KB per buffer

typedef unsigned long long ull;

__device__ __forceinline__ ull pk2(float lo, float hi) {
    ull r; asm("mov.b64 %0, {%1, %2};" : "=l"(r) : "f"(lo), "f"(hi)); return r;
}
__device__ __forceinline__ void upk2(ull v, float& lo, float& hi) {
    asm("mov.b64 {%0, %1}, %2;" : "=f"(lo), "=f"(hi) : "l"(v));
}
__device__ __forceinline__ ull ffma2(ull a, ull b, ull c) {
    ull d; asm("fma.rn.f32x2 %0, %1, %2, %3;" : "=l"(d) : "l"(a), "l"(b), "l"(c)); return d;
}
__device__ __forceinline__ ull fmul2(ull a, ull b) {
    ull d; asm("mul.rn.f32x2 %0, %1, %2;" : "=l"(d) : "l"(a), "l"(b)); return d;
}

__device__ __forceinline__ void cpasync16(uint32_t dst, const void* src) {
    asm volatile("cp.async.cg.shared.global [%0], [%1], 16;" :: "r"(dst), "l"(src));
}
#define CP_COMMIT() asm volatile("cp.async.commit_group;" ::: "memory")
#define CP_WAIT0()  asm volatile("cp.async.wait_group 0;" ::: "memory")

// Issue the 4 cp.asyncs that stage tile k of this channel into buf.
__device__ __forceinline__ void stage_cp(float* buf, const float* __restrict__ grow,
                                         int k, int tid) {
    uint32_t base = (uint32_t)__cvta_generic_to_shared(buf);
#pragma unroll
    for (int r = 0; r < 4; r++) {
        int j  = r * 128 + (tid >> 2);
        int i4 = (tid & 3) * 4;
        cpasync16(base + (uint32_t)(j * SSTRIDE + i4) * 4u,
                  grow + (size_t)j * CHUNK + k * TILE_I + i4);
    }
}

__global__ void __launch_bounds__(NT, 2)
pink_kernel(const float* __restrict__ white, float* __restrict__ out) {
    extern __shared__ float smem_raw[];          // 2 * BUF_FLOATS
    float* buf0 = smem_raw;
    float* buf1 = smem_raw + BUF_FLOATS;
    __shared__ float warpT[NW][6];
    __shared__ float warpW[NW][6];

    const float A0 = 0.99886f, A1 = 0.99332f, A2 = 0.969f,
                A3 = 0.8665f,  A4 = 0.55f,    A5 = -0.7616f;
    // output constants with OUT_GAIN=0.11 folded in
    const float OC0 = 0.11f * 0.0555179f, OC1 = 0.11f * 0.0750759f,
                OC2 = 0.11f * 0.153852f,  OC3 = 0.11f * 0.3104856f,
                OC4 = 0.11f * 0.5329522f, OC5 = 0.11f * -0.016898f;
    const float OB6 = 0.11f * 0.115926f, ODIR = 0.11f * 0.5362f;

    const int tid  = threadIdx.x;
    const int lane = tid & 31;
    const int wid  = tid >> 5;
    const float* wrow = white + (size_t)blockIdx.x * LROW;
    float*       orow = out   + (size_t)blockIdx.x * LROW;

    const ull A01 = pk2(A0, A1), A23 = pk2(A2, A3), A45 = pk2(A4, A5);

    // ---------------- Pass A: particular state from zero init ----------------
    stage_cp(buf0, wrow, 0, tid); CP_COMMIT();

    ull U01 = 0ull, U23 = 0ull, U45 = 0ull;
    for (int k = 0; k < NTILES; k++) {
        CP_WAIT0();
        __syncthreads();
        if (k + 1 < NTILES) {
            stage_cp((k & 1) ? buf0 : buf1, wrow, k + 1, tid); CP_COMMIT();
        } else {
            // prefetch pass-B tile 0 (hidden behind the scan)
            stage_cp(buf0, wrow, 0, tid); CP_COMMIT();
        }
        const float4* src = reinterpret_cast<const float4*>(
            ((k & 1) ? buf1 : buf0) + tid * SSTRIDE);
#pragma unroll
        for (int q = 0; q < 4; q++) {
            float4 wv = src[q];
            float ws[4] = {wv.x, wv.y, wv.z, wv.w};
#pragma unroll
            for (int c = 0; c < 4; c++) {
                ull W = pk2(ws[c], ws[c]);
                U01 = ffma2(A01, U01, W);
                U23 = ffma2(A23, U23, W);
                U45 = ffma2(A45, U45, W);
            }
        }
    }

    // b6 feed for pass B (issue the load early; latency hidden by the scan)
    float prev_w = (tid == 0) ? 0.f : wrow[tid * CHUNK - 1];

    // ---------------- Block scan over chunk states (u-space) ----------------
    float p[6];
    upk2(U01, p[0], p[1]); upk2(U23, p[2], p[3]); upk2(U45, p[4], p[5]);
    float m[6];                         // a_i^128 via 7 squarings
    {
        const float a[6] = {A0, A1, A2, A3, A4, A5};
#pragma unroll
        for (int i = 0; i < 6; i++) {
            float t = a[i];
#pragma unroll
            for (int s = 0; s < 7; s++) t *= t;
            m[i] = t;
        }
    }
    float mult[6];
#pragma unroll
    for (int i = 0; i < 6; i++) mult[i] = m[i];

    // warp-level inclusive scan: S_l = m*S_{l-1} + P_l
#pragma unroll
    for (int o = 1; o < 32; o <<= 1) {
#pragma unroll
        for (int i = 0; i < 6; i++) {
            float up = __shfl_up_sync(0xffffffffu, p[i], o);
            if (lane >= o) p[i] = fmaf(mult[i], up, p[i]);
            mult[i] *= mult[i];
        }
    }
    // now mult[i] == m[i]^32
    float excl[6];
#pragma unroll
    for (int i = 0; i < 6; i++) {
        float e = __shfl_up_sync(0xffffffffu, p[i], 1);
        excl[i] = (lane == 0) ? 0.f : e;
    }
    if (lane == 31) {
#pragma unroll
        for (int i = 0; i < 6; i++) warpT[wid][i] = p[i];
    }
    __syncthreads();

    if (wid == 0) {
        float t[6], cm[6];
#pragma unroll
        for (int i = 0; i < 6; i++) {
            t[i]  = (lane < NW) ? warpT[lane][i] : 0.f;
            cm[i] = mult[i];            // m^32
        }
#pragma unroll
        for (int o = 1; o < NW; o <<= 1) {
#pragma unroll
            for (int i = 0; i < 6; i++) {
                float up = __shfl_up_sync(0xffffffffu, t[i], o);
                if (lane >= o) t[i] = fmaf(cm[i], up, t[i]);
                cm[i] *= cm[i];
            }
        }
        if (lane < NW) {
#pragma unroll
            for (int i = 0; i < 6; i++) warpW[lane][i] = t[i];
        }
    }
    __syncthreads();

    // entry state for this chunk: excl + m^lane * (state after previous warps)
    float E[6];
#pragma unroll
    for (int i = 0; i < 6; i++) {
        float b = m[i], r = 1.f;
        int e = lane;
#pragma unroll
        for (int s = 0; s < 5; s++) { if (e & 1) r *= b; b *= b; e >>= 1; }
        E[i] = excl[i] + ((wid == 0) ? 0.f : r * warpW[wid - 1][i]);
    }

    // ---------------- Pass B: exact recompute + output ----------------
    U01 = pk2(E[0], E[1]); U23 = pk2(E[2], E[3]); U45 = pk2(E[4], E[5]);
    const ull C01 = pk2(OC0, OC1), C23 = pk2(OC2, OC3), C45 = pk2(OC4, OC5);

    for (int k = 0; k < NTILES; k++) {
        float* bufk = (k & 1) ? buf1 : buf0;
        CP_WAIT0();
        __syncthreads();                     // tile k visible; prior STG reads done
        if (k + 1 < NTILES) {
            stage_cp((k & 1) ? buf0 : buf1, wrow, k + 1, tid); CP_COMMIT();
        }
        float4* srcv = reinterpret_cast<float4*>(bufk + tid * SSTRIDE);
#pragma unroll
        for (int q = 0; q < 4; q++) {
            float4 wv = srcv[q];
            float ws[4] = {wv.x, wv.y, wv.z, wv.w};
            float o4[4];
#pragma unroll
            for (int c = 0; c < 4; c++) {
                float w = ws[c];
                ull W = pk2(w, w);
                U01 = ffma2(A01, U01, W);
                U23 = ffma2(A23, U23, W);
                U45 = ffma2(A45, U45, W);
                ull P = ffma2(C01, U01, ffma2(C23, U23, fmul2(C45, U45)));
                float plo, phi;
                upk2(P, plo, phi);
                float s = plo + phi;
                s = fmaf(OB6, prev_w, s);
                s = fmaf(ODIR, w, s);
                o4[c] = s;
                prev_w = w;
            }
            srcv[q] = make_float4(o4[0], o4[1], o4[2], o4[3]);
        }
        __syncthreads();                     // outputs in smem complete
#pragma unroll
        for (int r = 0; r < 4; r++) {
            int j  = r * 128 + (tid >> 2);
            int i4 = (tid & 3) * 4;
            float4 v = *reinterpret_cast<const float4*>(&bufk[j * SSTRIDE + i4]);
            *reinterpret_cast<float4*>(orow + (size_t)j * CHUNK + k * TILE_I + i4) = v;
        }
    }
}

extern "C" void kernel_launch(void* const* d_in, const int* in_sizes, int n_in,
                              void* d_out, int out_size) {
    const float* white = (const float*)d_in[0];
    float* out = (float*)d_out;
    int B = out_size / LROW;

    size_t smem = (size_t)2 * BUF_FLOATS * sizeof(float);   // 81920 bytes
    cudaFuncSetAttribute(pink_kernel, cudaFuncAttributeMaxDynamicSharedMemorySize,
                         (int)smem);
    pink_kernel<<<B, NT, smem>>>(white, out);
}

// round 6
// speedup vs baseline: 1.6772x; 1.1586x over previous
#include <cuda_runtime.h>
#include <cstdint>

// Pink noise: 6-pole diagonal IIR + 1-sample delay, exact segment-resident scan.
// white[B, L] -> pink[B, L], L=65536, one block per channel.
//
// v4 (resubmit — round 5 failed on container infra, not the kernel):
// segment-resident design. Each 16384-sample segment is fetched ONCE into
// smem (one coalesced cp.async burst), pass A + block scan + pass B all run on
// the resident copy (pass B overwrites in place), then one coalesced writeout.
// Exact cross-segment state carried in registers: segState' = a^16384*segState + T.

#define NT      512
#define CHUNK   32                    // samples per thread per segment
#define SEG     16384
#define NSEG    4                     // LROW / SEG
#define LROW    65536
#define SSTRIDE 36                    // conflict-free for float4 row access + coalesced staging
#define NW      (NT / 32)             // 16 warps
#define TILE_FLOATS (NT * SSTRIDE)    // 18432 floats = 73728 B

typedef unsigned long long ull;

__device__ __forceinline__ ull pk2(float lo, float hi) {
    ull r; asm("mov.b64 %0, {%1, %2};" : "=l"(r) : "f"(lo), "f"(hi)); return r;
}
__device__ __forceinline__ void upk2(ull v, float& lo, float& hi) {
    asm("mov.b64 {%0, %1}, %2;" : "=f"(lo), "=f"(hi) : "l"(v));
}
__device__ __forceinline__ ull ffma2(ull a, ull b, ull c) {
    ull d; asm("fma.rn.f32x2 %0, %1, %2, %3;" : "=l"(d) : "l"(a), "l"(b), "l"(c)); return d;
}
__device__ __forceinline__ ull fmul2(ull a, ull b) {
    ull d; asm("mul.rn.f32x2 %0, %1, %2;" : "=l"(d) : "l"(a), "l"(b)); return d;
}

__device__ __forceinline__ void cpasync16(uint32_t dst, const void* src) {
    asm volatile("cp.async.cg.shared.global [%0], [%1], 16;" :: "r"(dst), "l"(src));
}
#define CP_COMMIT() asm volatile("cp.async.commit_group;" ::: "memory")
#define CP_WAIT0()  asm volatile("cp.async.wait_group 0;" ::: "memory")

// Stage one full segment (64KB) into the tile: fully coalesced 16B cp.asyncs.
// float4 index f -> row j=f>>3 (8 float4 per 32-sample row), word i4=(f&7)*4.
__device__ __forceinline__ void stage_seg(float* tile, const float* __restrict__ gseg,
                                          int tid) {
    uint32_t base = (uint32_t)__cvta_generic_to_shared(tile);
#pragma unroll
    for (int r = 0; r < 8; r++) {
        int f  = tid + r * NT;
        int j  = f >> 3;
        int i4 = (f & 7) * 4;
        cpasync16(base + (uint32_t)(j * SSTRIDE + i4) * 4u, gseg + (size_t)f * 4);
    }
}

__global__ void __launch_bounds__(NT, 2)
pink_kernel(const float* __restrict__ white, float* __restrict__ out) {
    extern __shared__ float tile[];               // TILE_FLOATS
    __shared__ float warpT[NW][6];
    __shared__ float warpW[NW][6];

    const float A0 = 0.99886f, A1 = 0.99332f, A2 = 0.969f,
                A3 = 0.8665f,  A4 = 0.55f,    A5 = -0.7616f;
    const float OC0 = 0.11f * 0.0555179f, OC1 = 0.11f * 0.0750759f,
                OC2 = 0.11f * 0.153852f,  OC3 = 0.11f * 0.3104856f,
                OC4 = 0.11f * 0.5329522f, OC5 = 0.11f * -0.016898f;
    const float OB6 = 0.11f * 0.115926f, ODIR = 0.11f * 0.5362f;

    const int tid  = threadIdx.x;
    const int lane = tid & 31;
    const int wid  = tid >> 5;
    const float* wrow = white + (size_t)blockIdx.x * LROW;
    float*       orow = out   + (size_t)blockIdx.x * LROW;

    // Kick the first segment fetch immediately; power tables compute under it.
    stage_seg(tile, wrow, tid);
    CP_COMMIT();

    const ull A01 = pk2(A0, A1), A23 = pk2(A2, A3), A45 = pk2(A4, A5);
    const ull C01 = pk2(OC0, OC1), C23 = pk2(OC2, OC3), C45 = pk2(OC4, OC5);
    const ull ODB = pk2(ODIR, OB6);

    // m = a^32 (chunk multiplier); mlane = m^lane; m32w = (m^32)^wid.
    float m[6], mlane[6], m32w[6];
    {
        const float a[6] = {A0, A1, A2, A3, A4, A5};
#pragma unroll
        for (int i = 0; i < 6; i++) {
            float t = a[i];
#pragma unroll
            for (int s = 0; s < 5; s++) t *= t;
            m[i] = t;                                  // a^32
            // mlane = m^lane (lane < 32)
            float b = t, r = 1.f; int e = lane;
#pragma unroll
            for (int s = 0; s < 5; s++) { if (e & 1) r *= b; b *= b; e >>= 1; }
            mlane[i] = r;
            // b is now m^32; m32w = (m^32)^wid (wid < 16)
            float b2 = b, r2 = 1.f; int e2 = wid;
#pragma unroll
            for (int s = 0; s < 4; s++) { if (e2 & 1) r2 *= b2; b2 *= b2; e2 >>= 1; }
            m32w[i] = r2;
        }
    }

    float segState[6] = {0.f, 0.f, 0.f, 0.f, 0.f, 0.f};
    float w_carry = 0.f;

    for (int s = 0; s < NSEG; s++) {
        CP_WAIT0();
        __syncthreads();                              // segment resident

        // ---------------- Pass A: particular state from zero init ----------------
        ull U01 = 0ull, U23 = 0ull, U45 = 0ull;
        {
            const float4* src = reinterpret_cast<const float4*>(tile + tid * SSTRIDE);
#pragma unroll
            for (int q = 0; q < 8; q++) {
                float4 wv = src[q];
                float ws[4] = {wv.x, wv.y, wv.z, wv.w};
#pragma unroll
                for (int c = 0; c < 4; c++) {
                    ull W = pk2(ws[c], ws[c]);
                    U01 = ffma2(A01, U01, W);
                    U23 = ffma2(A23, U23, W);
                    U45 = ffma2(A45, U45, W);
                }
            }
        }

        // ---------------- Block scan over chunk states ----------------
        float p[6];
        upk2(U01, p[0], p[1]); upk2(U23, p[2], p[3]); upk2(U45, p[4], p[5]);
        float mult[6];
#pragma unroll
        for (int i = 0; i < 6; i++) mult[i] = m[i];

#pragma unroll
        for (int o = 1; o < 32; o <<= 1) {
#pragma unroll
            for (int i = 0; i < 6; i++) {
                float up = __shfl_up_sync(0xffffffffu, p[i], o);
                if (lane >= o) p[i] = fmaf(mult[i], up, p[i]);
                mult[i] *= mult[i];
            }
        }
        // mult == m^32 now
        float excl[6];
#pragma unroll
        for (int i = 0; i < 6; i++) {
            float e = __shfl_up_sync(0xffffffffu, p[i], 1);
            excl[i] = (lane == 0) ? 0.f : e;
        }
        if (lane == 31) {
#pragma unroll
            for (int i = 0; i < 6; i++) warpT[wid][i] = p[i];
        }
        __syncthreads();

        if (wid == 0) {
            float t[6], cm[6];
#pragma unroll
            for (int i = 0; i < 6; i++) {
                t[i]  = (lane < NW) ? warpT[lane][i] : 0.f;
                cm[i] = mult[i];                      // m^32
            }
#pragma unroll
            for (int o = 1; o < NW; o <<= 1) {
#pragma unroll
                for (int i = 0; i < 6; i++) {
                    float up = __shfl_up_sync(0xffffffffu, t[i], o);
                    if (lane >= o) t[i] = fmaf(cm[i], up, t[i]);
                    cm[i] *= cm[i];
                }
            }
            if (lane < NW) {
#pragma unroll
                for (int i = 0; i < 6; i++) warpW[lane][i] = t[i];
            }
        }
        __syncthreads();

        // Exact chunk entry: excl + m^lane * (prev-warp total + m32^wid * segState)
        float E[6];
#pragma unroll
        for (int i = 0; i < 6; i++) {
            float pw = (wid == 0) ? 0.f : warpW[wid - 1][i];
            E[i] = fmaf(mlane[i], fmaf(m32w[i], segState[i], pw), excl[i]);
        }

        // Segment bookkeeping while tile still holds white:
        float prev_w = (tid == 0) ? w_carry : tile[(tid - 1) * SSTRIDE + (CHUNK - 1)];
        float w_next = tile[(NT - 1) * SSTRIDE + (CHUNK - 1)];
        // segState' = m^512 * segState + T  (T = whole-segment particular state)
#pragma unroll
        for (int i = 0; i < 6; i++) {
            float d = m[i];
#pragma unroll
            for (int sq = 0; sq < 9; sq++) d *= d;    // m^512 = a^16384
            segState[i] = fmaf(d, segState[i], warpW[NW - 1][i]);
        }
        __syncthreads();                              // prev_w reads done before overwrite

        // ---------------- Pass B: exact recompute, in-place overwrite ----------------
        U01 = pk2(E[0], E[1]); U23 = pk2(E[2], E[3]); U45 = pk2(E[4], E[5]);
        {
            float4* sv = reinterpret_cast<float4*>(tile + tid * SSTRIDE);
#pragma unroll
            for (int q = 0; q < 8; q++) {
                float4 wv = sv[q];
                float ws[4] = {wv.x, wv.y, wv.z, wv.w};
                float o4[4];
#pragma unroll
                for (int c = 0; c < 4; c++) {
                    float w = ws[c];
                    ull W = pk2(w, w);
                    U01 = ffma2(A01, U01, W);
                    U23 = ffma2(A23, U23, W);
                    U45 = ffma2(A45, U45, W);
                    ull P = ffma2(C01, U01, ffma2(C23, U23, fmul2(C45, U45)));
                    // {ODIR*w + Plo, OB6*prev_w + Phi} then horizontal add
                    ull T2 = ffma2(ODB, pk2(w, prev_w), P);
                    float tlo, thi;
                    upk2(T2, tlo, thi);
                    o4[c] = tlo + thi;
                    prev_w = w;
                }
                sv[q] = make_float4(o4[0], o4[1], o4[2], o4[3]);
            }
        }
        w_carry = w_next;
        __syncthreads();                              // outputs complete in smem

        // ---------------- Coalesced writeout ----------------
#pragma unroll
        for (int r = 0; r < 8; r++) {
            int f  = tid + r * NT;
            int j  = f >> 3;
            int i4 = (f & 7) * 4;
            float4 v = *reinterpret_cast<const float4*>(&tile[j * SSTRIDE + i4]);
            *reinterpret_cast<float4*>(orow + (size_t)s * SEG + (size_t)f * 4) = v;
        }
        __syncthreads();                              // writeout LDS done before refill

        if (s + 1 < NSEG) {
            stage_seg(tile, wrow + (size_t)(s + 1) * SEG, tid);
            CP_COMMIT();
        }
    }
}

extern "C" void kernel_launch(void* const* d_in, const int* in_sizes, int n_in,
                              void* d_out, int out_size) {
    const float* white = (const float*)d_in[0];
    float* out = (float*)d_out;
    int B = out_size / LROW;

    size_t smem = (size_t)TILE_FLOATS * sizeof(float);   // 73728 bytes
    cudaFuncSetAttribute(pink_kernel, cudaFuncAttributeMaxDynamicSharedMemorySize,
                         (int)smem);
    pink_kernel<<<B, NT, smem>>>(white, out);
}